// round 15
// baseline (speedup 1.0000x reference)
#include <cuda_runtime.h>
#include <cstdint>

// ---------------- problem constants ----------------
#define BB 1024
#define LL 128
#define PP 32
#define SPLITS 16
#define LPER   8                  // l's per split
#define MTILES 8                  // 1024/128
// symmetric-pair K: 528 real cols per l, padded to 576 = 18 chunks of 32
#define KPL    576
#define NCHL   18                 // chunks per l
#define NSTAGE (LPER * 3)         // 24 stages; stage = 6 chunks = 192 cols
#define NBUF   3

// ---------------- device scratch (allocation-free) ----------------
__device__ float    g_partial[SPLITS * BB * LL];     // 8 MB split-K partials
__device__ uint32_t g_Wt[128 * NCHL * 2048];         // 18.9 MB: 64*(W+W^T) fp16 images [l*18+c][n=128][k=32]

// ---------------- helpers ----------------
__device__ __forceinline__ uint32_t s2u(const void* p) {
    uint32_t a;
    asm("{ .reg .u64 t; cvta.to.shared.u64 t, %1; cvt.u32.u64 %0, t; }" : "=r"(a) : "l"(p));
    return a;
}
// pack two f32 -> f16x2 (lower half = lo, upper = hi)
__device__ __forceinline__ uint32_t pack_f16x2(float lo, float hi) {
    uint32_t r;
    asm("cvt.rn.f16x2.f32 %0, %1, %2;" : "=r"(r) : "f"(hi), "f"(lo));
    return r;
}
__device__ __forceinline__ void cp16(uint32_t sdst, const void* gsrc) {
    asm volatile("cp.async.cg.shared.global [%0], [%1], 16;" :: "r"(sdst), "l"(gsrc));
}
#define CP_COMMIT() asm volatile("cp.async.commit_group;")
#define CP_WAIT(n)  asm volatile("cp.async.wait_group %0;" :: "n"(n))

#define LDSM4(r, a)                                                              \
    asm volatile("ldmatrix.sync.aligned.m8n8.x4.shared.b16 {%0,%1,%2,%3}, [%4];" \
                 : "=r"((r)[0]), "=r"((r)[1]), "=r"((r)[2]), "=r"((r)[3])        \
                 : "r"(a))

__device__ __forceinline__ void mma_acc(float* d, const uint32_t* a, uint32_t b0, uint32_t b1) {
    asm("mma.sync.aligned.m16n8k16.row.col.f32.f16.f16.f32 "
        "{%0,%1,%2,%3},{%4,%5,%6,%7},{%8,%9},{%0,%1,%2,%3};"
        : "+f"(d[0]), "+f"(d[1]), "+f"(d[2]), "+f"(d[3])
        : "r"(a[0]), "r"(a[1]), "r"(a[2]), "r"(a[3]), "r"(b0), "r"(b1));
}

// k -> (i,j) pair table for upper-triangle row-major enumeration (i<=j)
__device__ __forceinline__ void build_tab(uint32_t* tab, int tid, int nthr) {
    for (int k = tid; k < KPL; k += nthr) {
        int i = 0, rem = k;
        #pragma unroll 1
        while (i < 31 && rem >= 32 - i) { rem -= 32 - i; i++; }
        int j = i + rem;
        if (k >= 528) { i = 0; j = 0; }     // pad region (B is zero there)
        tab[k] = ((uint32_t)i << 8) | (uint32_t)j;
    }
}

// ---------------- SMEM layout (main kernel) ----------------
// stage tile: [n=128][k=192 fp16] rows of 384B = 24 16B-units,
// XOR swizzle within each 8-unit (128B) block: u -> (u&~7) | ((u&7)^(n&7))
#define ROWB    384
#define BUF_SZ  (128 * ROWB)                  // 49152 per stage buffer
#define OFF_PS  (NBUF * BUF_SZ)               // 147456 : float pS[128][33]
#define OFF_CS  (OFF_PS + 128 * 33 * 4)       // float cS[128][9]
#define OFF_TAB (OFF_CS + 128 * 9 * 4)        // u32 tab[576]
#define SMEM_TOTAL (OFF_TAB + KPL * 4)        // 171264 bytes

// =====================================================================
// Prep: W fp32 [131072][128] -> symmetric-folded fp16(64*(Wij+Wji)) images
// block = (l, c): image [n=128][k=32 of the 576-col padded pair axis]
// =====================================================================
__global__ void __launch_bounds__(256) fipp_prep_kernel(const float* __restrict__ W)
{
    __shared__ uint32_t tab[KPL];
    const int tid = threadIdx.x;
    build_tab(tab, tid, 256);
    __syncthreads();

    const int blk = blockIdx.x;          // 0..128*18-1
    const int l = blk / NCHL, c = blk % NCHL;
    uint32_t* oh = g_Wt + (size_t)blk * 2048;
    #pragma unroll
    for (int v = 0; v < 8; v++) {
        const int e = v * 256 + tid;     // 0..2047
        const int q = e >> 7, n = e & 127;
        float vals[2];
        #pragma unroll
        for (int d = 0; d < 2; d++) {
            const int kk = 32 * c + 2 * q + d;
            float x = 0.0f;
            if (kk < 528) {
                const uint32_t ij = tab[kk];
                const int i = ij >> 8, j = ij & 255;
                x = W[(size_t)(l * 1024 + i * 32 + j) * 128 + n];
                if (i != j) x += W[(size_t)(l * 1024 + j * 32 + i) * 128 + n];
            }
            vals[d] = 64.0f * x;
        }
        oh[n * 16 + q] = pack_f16x2(vals[0], vals[1]);
    }
}

// =====================================================================
// Main: single fp16 HMMA GEMM over the symmetric pair axis.
// CTA: M=128 batch rows, N=128, K = 8 l's x 576 = 4608 (24 stages of 192).
// 8 warps, warp tile M=32 x N=64.
// =====================================================================
__global__ void __launch_bounds__(256, 1)
fipp_mma_kernel(const float* __restrict__ ctrl, const float* __restrict__ pert)
{
    extern __shared__ char smem[];
    float*    pS  = (float*)(smem + OFF_PS);   // [128][33]
    float*    cS  = (float*)(smem + OFF_CS);   // [128][9]
    uint32_t* tab = (uint32_t*)(smem + OFF_TAB);
    const uint32_t sb = s2u(smem);
    const int tid = threadIdx.x, wid = tid >> 5, lane = tid & 31;
    const int wm = wid & 3, wn = wid >> 2;   // 4 M-bands x 2 N-bands (32x64)
    const int g = lane >> 2, t = lane & 3;
    const int bm0 = blockIdx.x * 128, l_base = blockIdx.y * LPER;

    // stage loader: 6 chunk images (48KB) -> one [n=128][k=192] tile
    auto issueW = [&](int st, int buf) {
        const int l = st / 3, c0 = (st % 3) * 6;
        const uint32_t* gh = g_Wt + (size_t)((l_base + l) * NCHL + c0) * 2048;
        const uint32_t bbase = sb + (uint32_t)buf * BUF_SZ;
        #pragma unroll
        for (int q = 0; q < 12; q++) {
            const int e = q * 256 + tid;        // 0..3071 16B units
            const int cl = e >> 9, gi = e & 511;
            const int n = gi >> 2, w = gi & 3;
            const int ul = cl * 4 + w;          // unit 0..23 within row
            const uint32_t off = (uint32_t)(((ul >> 3) << 7) | ((((ul) & 7) ^ (n & 7)) << 4));
            cp16(bbase + (uint32_t)(n * ROWB) + off, gh + 4 * e);
        }
        CP_COMMIT();
    };

    issueW(0, 0);

    // one-time p (padded 33), c (padded 9), pair table
    for (int e = tid; e < 128 * 32; e += 256) {
        int r = e >> 5, j = e & 31;
        pS[r * 33 + j] = pert[(size_t)(bm0 + r) * PP + j];
    }
    for (int e = tid; e < 128 * 8; e += 256) {
        int r = e >> 3, q = e & 7;
        cS[r * 9 + q] = ctrl[(size_t)(bm0 + r) * LL + l_base + q];
    }
    build_tab(tab, tid, 256);

    issueW(1, 1);
    __syncthreads();   // pS/cS/tab ready

    // per-thread rows (4 rows: wm*32 + rr*8 + g)
    int rows[4];
    #pragma unroll
    for (int rr = 0; rr < 4; rr++) rows[rr] = wm * 32 + rr * 8 + g;

    float acc[2][8][4];
    #pragma unroll
    for (int m = 0; m < 2; m++)
        #pragma unroll
        for (int nt = 0; nt < 8; nt++)
            #pragma unroll
            for (int k = 0; k < 4; k++) acc[m][nt][k] = 0.f;

    float clv[4];

    // ldmatrix addressing: row base per lane + per-lane swizzle constants
    const int nlocal = ((lane >> 4) << 3) | (lane & 7);
    const int hk = (lane >> 3) & 1;          // 16B k-offset select
    const int sx = lane & 7;                 // swizzle XOR
    const uint32_t rba = (uint32_t)((wn * 64 + nlocal) * ROWB);

    for (int st = 0; st < NSTAGE; st++) {
        const int buf = st % NBUF;
        if (st + 2 < NSTAGE) { CP_WAIT(1); } else { CP_WAIT(0); }
        __syncthreads();
        if (st + 2 < NSTAGE) issueW(st + 2, (st + 2) % NBUF);

        const int l = st / 3, cbase = (st % 3) * 192;
        if (st % 3 == 0) {
            #pragma unroll
            for (int rr = 0; rr < 4; rr++) clv[rr] = cS[rows[rr] * 9 + l];
        }
        const uint32_t Bt = sb + (uint32_t)buf * BUF_SZ + rba;

        // fragment-group loader: gidx 0..11 (k16 groups within the 192 cols)
        auto ld_group = [&](int gidx, uint32_t* bh) {
            const int ustart = 2 * gidx + hk;
            const uint32_t uu = (uint32_t)(((ustart >> 3) << 7) | (((ustart & 7) ^ sx) << 4));
            #pragma unroll
            for (int ntp = 0; ntp < 4; ntp++)
                LDSM4(bh + 4 * ntp, Bt + (uint32_t)(ntp * 16 * ROWB) + uu);
        };

        uint32_t bhA[16], bhB[16];
        ld_group(0, bhA);

        #pragma unroll
        for (int gidx = 0; gidx < 12; gidx++) {
            uint32_t* cur = (gidx & 1) ? bhB : bhA;
            uint32_t* nxt = (gidx & 1) ? bhA : bhB;
            if (gidx + 1 < 12) ld_group(gidx + 1, nxt);

            // A build: a(row, k) = c_l * p[i(k)] * p[j(k)], 4 k's per thread
            const int kb = cbase + (gidx << 4) + 2 * t;
            const uint32_t ij0 = tab[kb],     ij1 = tab[kb + 1];
            const uint32_t ij2 = tab[kb + 8], ij3 = tab[kb + 9];
            const int i0 = ij0 >> 8, j0 = ij0 & 255;
            const int i1 = ij1 >> 8, j1 = ij1 & 255;
            const int i2 = ij2 >> 8, j2 = ij2 & 255;
            const int i3 = ij3 >> 8, j3 = ij3 & 255;

            uint32_t a[2][4];
            #pragma unroll
            for (int m = 0; m < 2; m++)
                #pragma unroll
                for (int r4 = 0; r4 < 4; r4++) {
                    const int rr = 2 * m + (r4 & 1);
                    const float* pr = pS + rows[rr] * 33;
                    const float cl = clv[rr];
                    float v0, v1;
                    if ((r4 >> 1) == 0) { v0 = cl * pr[i0] * pr[j0]; v1 = cl * pr[i1] * pr[j1]; }
                    else                { v0 = cl * pr[i2] * pr[j2]; v1 = cl * pr[i3] * pr[j3]; }
                    a[m][r4] = pack_f16x2(v0, v1);
                }

            #pragma unroll
            for (int m = 0; m < 2; m++)
                #pragma unroll
                for (int nt = 0; nt < 8; nt++)
                    mma_acc(acc[m][nt], a[m], cur[2 * nt], cur[2 * nt + 1]);
        }
    }

    // epilogue -> split-K partials (undo the *64 on W)
    #pragma unroll
    for (int m = 0; m < 2; m++)
        #pragma unroll
        for (int rh = 0; rh < 2; rh++) {
            const int rowloc = wm * 32 + m * 16 + rh * 8 + g;
            float* dst = g_partial + ((size_t)blockIdx.y * BB + bm0 + rowloc) * LL;
            #pragma unroll
            for (int nt = 0; nt < 8; nt++) {
                const int col = wn * 64 + nt * 8 + 2 * t;
                float2 v;
                v.x = acc[m][nt][rh ? 2 : 0] * 0.015625f;
                v.y = acc[m][nt][rh ? 3 : 1] * 0.015625f;
                *(float2*)(dst + col) = v;
            }
        }
}

// =====================================================================
// Reduce: sum 16 split-K partials + bias
// =====================================================================
__global__ void __launch_bounds__(256)
fipp_reduce_kernel(const float* __restrict__ bias, float* __restrict__ out)
{
    const int i4 = blockIdx.x * blockDim.x + threadIdx.x;
    float4 acc = *(const float4*)(bias + ((i4 * 4) & (LL - 1)));
    #pragma unroll
    for (int s = 0; s < SPLITS; s++) {
        const float4 v = *(const float4*)(g_partial + (size_t)s * (BB * LL) + (size_t)i4 * 4);
        acc.x += v.x; acc.y += v.y; acc.z += v.z; acc.w += v.w;
    }
    *(float4*)(out + (size_t)i4 * 4) = acc;
}

extern "C" void kernel_launch(void* const* d_in, const int* in_sizes, int n_in,
                              void* d_out, int out_size)
{
    const float* ctrl = (const float*)d_in[0];   // (1024,128)
    const float* pert = (const float*)d_in[1];   // (1024,32)
    const float* W    = (const float*)d_in[2];   // (131072,128)
    const float* bias = (const float*)d_in[3];   // (128,)
    float* out = (float*)d_out;                  // (1024,128)

    cudaFuncSetAttribute(fipp_mma_kernel,
                         cudaFuncAttributeMaxDynamicSharedMemorySize, SMEM_TOTAL);

    fipp_prep_kernel<<<128 * NCHL, 256>>>(W);
    fipp_mma_kernel<<<dim3(MTILES, SPLITS), 256, SMEM_TOTAL>>>(ctrl, pert);
    fipp_reduce_kernel<<<(BB * LL) / 4 / 256, 256>>>(bias, out);
}

// round 16
// speedup vs baseline: 1.2591x; 1.2591x over previous
#include <cuda_runtime.h>
#include <cstdint>

// ---------------- problem constants ----------------
#define BB 1024
#define LL 128
#define PP 32
#define SPLITS 16
#define LPER   8                  // l's per split
#define MTILES 8                  // 1024/128
// octet-aligned symmetric pair axis: 80 octets = 640 cols per l (20 chunks of 32)
#define NOCT   80
#define KCHL   20                 // chunks per l
#define NSTAGE (LPER * 5)         // 40 stages; stage = 4 chunks = 128 cols = 16 octets
#define NBUF   3
#define PSTR   41                 // padded pS row stride (floats)

// ---------------- device scratch (allocation-free) ----------------
__device__ float    g_partial[SPLITS * BB * LL];     // 8 MB split-K partials
__device__ uint32_t g_Wt[128 * KCHL * 2048];         // 21 MB: 64*(W+W^T) fp16 images [l*20+c][n=128][k=32]

// ---------------- helpers ----------------
__device__ __forceinline__ uint32_t s2u(const void* p) {
    uint32_t a;
    asm("{ .reg .u64 t; cvta.to.shared.u64 t, %1; cvt.u32.u64 %0, t; }" : "=r"(a) : "l"(p));
    return a;
}
// pack two f32 -> f16x2 (lower half = lo, upper = hi)
__device__ __forceinline__ uint32_t pack_f16x2(float lo, float hi) {
    uint32_t r;
    asm("cvt.rn.f16x2.f32 %0, %1, %2;" : "=r"(r) : "f"(hi), "f"(lo));
    return r;
}
__device__ __forceinline__ void cp16(uint32_t sdst, const void* gsrc) {
    asm volatile("cp.async.cg.shared.global [%0], [%1], 16;" :: "r"(sdst), "l"(gsrc));
}
#define CP_COMMIT() asm volatile("cp.async.commit_group;")
#define CP_WAIT(n)  asm volatile("cp.async.wait_group %0;" :: "n"(n))

#define LDSM4(r, a)                                                              \
    asm volatile("ldmatrix.sync.aligned.m8n8.x4.shared.b16 {%0,%1,%2,%3}, [%4];" \
                 : "=r"((r)[0]), "=r"((r)[1]), "=r"((r)[2]), "=r"((r)[3])        \
                 : "r"(a))

__device__ __forceinline__ void mma_acc(float* d, const uint32_t* a, uint32_t b0, uint32_t b1) {
    asm("mma.sync.aligned.m16n8k16.row.col.f32.f16.f16.f32 "
        "{%0,%1,%2,%3},{%4,%5,%6,%7},{%8,%9},{%0,%1,%2,%3};"
        : "+f"(d[0]), "+f"(d[1]), "+f"(d[2]), "+f"(d[3])
        : "r"(a[0]), "r"(a[1]), "r"(a[2]), "r"(a[3]), "r"(b0), "r"(b1));
}

// octet table: for i=0..31, jb=i,i+8,.. (<32): entry = i<<8 | jb. 80 entries.
__device__ __forceinline__ void build_oct(uint32_t* oct) {
    int o = 0;
    for (int i = 0; i < 32; i++)
        for (int jb = i; jb < 32; jb += 8)
            oct[o++] = ((uint32_t)i << 8) | (uint32_t)jb;
}

// ---------------- SMEM layout (main kernel) ----------------
#define ROWB    256
#define BUF_SZ  (128 * ROWB)                  // 32768 per stage buffer
#define OFF_PS  (NBUF * BUF_SZ)               // 98304 : float pS[128][41] zero-padded
#define OFF_CS  (OFF_PS + 128 * PSTR * 4)     // float cS[128][9]
#define OFF_TAB (OFF_CS + 128 * 9 * 4)        // u32 oct[80]
#define SMEM_TOTAL (OFF_TAB + NOCT * 4)       // 124224 bytes

// =====================================================================
// Prep: coalesced symmetric fold. block = (l, chunk c of 32 kk-cols).
// For each kk: read rows W[l,i,j,:] (+ W[l,j,i,:]) coalesced across 128
// threads, stage in SMEM, emit fp16(64*(Wij+Wji)) image [n=128][k=32].
// =====================================================================
__global__ void __launch_bounds__(128) fipp_prep_kernel(const float* __restrict__ W)
{
    __shared__ uint32_t oct[NOCT];
    __shared__ float sbuf[32][129];
    const int tid = threadIdx.x;
    if (tid == 0) build_oct(oct);
    __syncthreads();

    const int l = blockIdx.x / KCHL, c = blockIdx.x % KCHL;
    #pragma unroll 4
    for (int kk = 0; kk < 32; kk++) {
        const int kg = 32 * c + kk;
        const uint32_t e = oct[kg >> 3];
        const int i = e >> 8, j = (int)(e & 255) + (kg & 7);
        float v = 0.0f;
        if (j < 32) {
            v = W[(size_t)(l * 1024 + i * 32 + j) * 128 + tid];
            if (i != j) v += W[(size_t)(l * 1024 + j * 32 + i) * 128 + tid];
        }
        sbuf[kk][tid] = 64.0f * v;
    }
    __syncthreads();

    // write image: thread n=tid emits 16 u32 (64B) contiguous
    uint32_t* oh = g_Wt + (size_t)blockIdx.x * 2048 + tid * 16;
    #pragma unroll
    for (int v4 = 0; v4 < 4; v4++) {
        uint32_t r[4];
        #pragma unroll
        for (int d = 0; d < 4; d++) {
            const int q = v4 * 4 + d;
            r[d] = pack_f16x2(sbuf[2 * q][tid], sbuf[2 * q + 1][tid]);
        }
        *(uint4*)(oh + v4 * 4) = make_uint4(r[0], r[1], r[2], r[3]);
    }
}

// =====================================================================
// Main: fp16 HMMA GEMM over octet-aligned symmetric pair axis.
// CTA: M=128, N=128, K = 8 l x 640 (40 stages of 128 cols).
// 8 warps, warp tile M=32 x N=64. A + B fragment groups double-buffered.
// =====================================================================
__global__ void __launch_bounds__(256, 1)
fipp_mma_kernel(const float* __restrict__ ctrl, const float* __restrict__ pert)
{
    extern __shared__ char smem[];
    float*    pS  = (float*)(smem + OFF_PS);   // [128][41] zero-padded
    float*    cS  = (float*)(smem + OFF_CS);   // [128][9]
    uint32_t* tab = (uint32_t*)(smem + OFF_TAB);
    const uint32_t sb = s2u(smem);
    const int tid = threadIdx.x, wid = tid >> 5, lane = tid & 31;
    const int wm = wid & 3, wn = wid >> 2;   // 4 M-bands x 2 N-bands (32x64)
    const int g = lane >> 2, t = lane & 3;
    const int bm0 = blockIdx.x * 128, l_base = blockIdx.y * LPER;

    // stage loader: 4 chunk images (32KB) -> [n=128][k=128] tile, swizzled
    auto issueW = [&](int st, int buf) {
        const int l = st / 5, c0 = (st % 5) * 4;
        const uint32_t* gh = g_Wt + (size_t)((l_base + l) * KCHL + c0) * 2048;
        const uint32_t bbase = sb + (uint32_t)buf * BUF_SZ;
        #pragma unroll
        for (int q = 0; q < 8; q++) {
            const int e = q * 256 + tid;        // 0..2047 16B units
            const int c = e >> 9, gi = e & 511;
            const int n = gi >> 2, w4 = gi & 3;
            const int u = ((4 * c + w4) ^ (n & 7));
            cp16(bbase + (uint32_t)(n * ROWB + (u << 4)), gh + 4 * e);
        }
        CP_COMMIT();
    };

    issueW(0, 0);

    // one-time fills: pS (zero-padded), cS, octet table
    for (int e = tid; e < 128 * PSTR; e += 256) {
        const int r = e / PSTR, j = e % PSTR;
        pS[e] = (j < 32) ? pert[(size_t)(bm0 + r) * PP + j] : 0.0f;
    }
    for (int e = tid; e < 128 * 8; e += 256) {
        const int r = e >> 3, q = e & 7;
        cS[r * 9 + q] = ctrl[(size_t)(bm0 + r) * LL + l_base + q];
    }
    if (tid == 0) build_oct(tab);

    issueW(1, 1);
    __syncthreads();   // pS/cS/tab ready

    int rows[4];
    #pragma unroll
    for (int rr = 0; rr < 4; rr++) rows[rr] = wm * 32 + rr * 8 + g;

    float acc[2][8][4];
    #pragma unroll
    for (int m = 0; m < 2; m++)
        #pragma unroll
        for (int nt = 0; nt < 8; nt++)
            #pragma unroll
            for (int k = 0; k < 4; k++) acc[m][nt][k] = 0.f;

    float clv[4];

    // ldmatrix addressing
    const int nlocal = ((lane >> 4) << 3) | (lane & 7);
    const int hk = (lane >> 3) & 1;
    const int sx = lane & 7;
    const uint32_t rba = (uint32_t)((wn * 64 + nlocal) * ROWB);

    for (int st = 0; st < NSTAGE; st++) {
        const int buf = st % NBUF;
        if (st + 2 < NSTAGE) { CP_WAIT(1); } else { CP_WAIT(0); }
        __syncthreads();
        if (st + 2 < NSTAGE) issueW(st + 2, (st + 2) % NBUF);

        const int l = st / 5, stq = st % 5;
        const int obase = stq * 16;
        if (stq == 0) {
            #pragma unroll
            for (int rr = 0; rr < 4; rr++) clv[rr] = cS[rows[rr] * 9 + l];
        }
        const uint32_t Bt = sb + (uint32_t)buf * BUF_SZ + rba;

        auto ld_group = [&](int gidx, uint32_t* bh) {
            const uint32_t uu = (uint32_t)(((gidx << 1) + hk) ^ sx) << 4;
            #pragma unroll
            for (int ntp = 0; ntp < 4; ntp++)
                LDSM4(bh + 4 * ntp, Bt + (uint32_t)(ntp * 16 * ROWB) + uu);
        };
        // A build: octet pair (o0 = low 8 k's, o1 = high 8 k's) of group gidx
        auto a_build = [&](int gidx, uint32_t* av) {  // av[8] = a[m][r4]
            const uint32_t e0 = tab[obase + 2 * gidx];
            const uint32_t e1 = tab[obase + 2 * gidx + 1];
            const int i0 = e0 >> 8, j0 = (int)(e0 & 255) + 2 * t;
            const int i1 = e1 >> 8, j1 = (int)(e1 & 255) + 2 * t;
            #pragma unroll
            for (int rr = 0; rr < 4; rr++) {
                const float* pr = pS + rows[rr] * PSTR;
                const float s0 = clv[rr] * pr[i0];
                const float s1 = clv[rr] * pr[i1];
                av[(rr >> 1) * 4 + (rr & 1)]     = pack_f16x2(s0 * pr[j0], s0 * pr[j0 + 1]);
                av[(rr >> 1) * 4 + 2 + (rr & 1)] = pack_f16x2(s1 * pr[j1], s1 * pr[j1 + 1]);
            }
        };

        uint32_t bA[16], bB[16], aA[8], aB[8];
        ld_group(0, bA);
        a_build(0, aA);

        #pragma unroll
        for (int gidx = 0; gidx < 8; gidx++) {
            uint32_t* curB = (gidx & 1) ? bB : bA;
            uint32_t* nxtB = (gidx & 1) ? bA : bB;
            uint32_t* curA = (gidx & 1) ? aB : aA;
            uint32_t* nxtA = (gidx & 1) ? aA : aB;
            if (gidx + 1 < 8) { ld_group(gidx + 1, nxtB); a_build(gidx + 1, nxtA); }

            #pragma unroll
            for (int m = 0; m < 2; m++)
                #pragma unroll
                for (int nt = 0; nt < 8; nt++)
                    mma_acc(acc[m][nt], curA + 4 * m, curB[2 * nt], curB[2 * nt + 1]);
        }
    }

    // epilogue -> split-K partials (undo the *64 on W)
    #pragma unroll
    for (int m = 0; m < 2; m++)
        #pragma unroll
        for (int rh = 0; rh < 2; rh++) {
            const int rowloc = wm * 32 + m * 16 + rh * 8 + g;
            float* dst = g_partial + ((size_t)blockIdx.y * BB + bm0 + rowloc) * LL;
            #pragma unroll
            for (int nt = 0; nt < 8; nt++) {
                const int col = wn * 64 + nt * 8 + 2 * t;
                float2 v;
                v.x = acc[m][nt][rh ? 2 : 0] * 0.015625f;
                v.y = acc[m][nt][rh ? 3 : 1] * 0.015625f;
                *(float2*)(dst + col) = v;
            }
        }
}

// =====================================================================
// Reduce: sum 16 split-K partials + bias
// =====================================================================
__global__ void __launch_bounds__(256)
fipp_reduce_kernel(const float* __restrict__ bias, float* __restrict__ out)
{
    const int i4 = blockIdx.x * blockDim.x + threadIdx.x;
    float4 acc = *(const float4*)(bias + ((i4 * 4) & (LL - 1)));
    #pragma unroll
    for (int s = 0; s < SPLITS; s++) {
        const float4 v = *(const float4*)(g_partial + (size_t)s * (BB * LL) + (size_t)i4 * 4);
        acc.x += v.x; acc.y += v.y; acc.z += v.z; acc.w += v.w;
    }
    *(float4*)(out + (size_t)i4 * 4) = acc;
}

extern "C" void kernel_launch(void* const* d_in, const int* in_sizes, int n_in,
                              void* d_out, int out_size)
{
    const float* ctrl = (const float*)d_in[0];   // (1024,128)
    const float* pert = (const float*)d_in[1];   // (1024,32)
    const float* W    = (const float*)d_in[2];   // (131072,128)
    const float* bias = (const float*)d_in[3];   // (128,)
    float* out = (float*)d_out;                  // (1024,128)

    cudaFuncSetAttribute(fipp_mma_kernel,
                         cudaFuncAttributeMaxDynamicSharedMemorySize, SMEM_TOTAL);

    fipp_prep_kernel<<<128 * KCHL, 128>>>(W);
    fipp_mma_kernel<<<dim3(MTILES, SPLITS), 256, SMEM_TOTAL>>>(ctrl, pert);
    fipp_reduce_kernel<<<(BB * LL) / 4 / 256, 256>>>(bias, out);
}

// round 17
// speedup vs baseline: 1.3038x; 1.0355x over previous
#include <cuda_runtime.h>
#include <cstdint>

// ---------------- problem constants ----------------
#define BB 1024
#define LL 128
#define PP 32
#define SPLITS 16
#define LPER   8                  // l's per split
#define MTILES 8                  // 1024/128
// octet-aligned symmetric pair axis: 80 octets = 640 cols per l (20 chunks of 32)
#define NOCT   80
#define KCHL   20                 // chunks per l
#define NSTAGE (LPER * 5)         // 40 stages; stage = 4 chunks = 128 cols = 16 octets
#define NBUF   3
#define PSTR   41                 // padded pS row stride (floats)

// ---------------- device scratch (allocation-free) ----------------
__device__ float    g_partial[SPLITS * BB * LL];     // 8 MB split-K partials
__device__ uint32_t g_Wt[128 * KCHL * 2048];         // 21 MB: 64*(W+W^T) fp16 images [l*20+c][n=128][k=32]

// ---------------- helpers ----------------
__device__ __forceinline__ uint32_t s2u(const void* p) {
    uint32_t a;
    asm("{ .reg .u64 t; cvta.to.shared.u64 t, %1; cvt.u32.u64 %0, t; }" : "=r"(a) : "l"(p));
    return a;
}
// pack two f32 -> f16x2 (lower half = lo, upper = hi)
__device__ __forceinline__ uint32_t pack_f16x2(float lo, float hi) {
    uint32_t r;
    asm("cvt.rn.f16x2.f32 %0, %1, %2;" : "=r"(r) : "f"(hi), "f"(lo));
    return r;
}
__device__ __forceinline__ void cp16(uint32_t sdst, const void* gsrc) {
    asm volatile("cp.async.cg.shared.global [%0], [%1], 16;" :: "r"(sdst), "l"(gsrc));
}
#define CP_COMMIT() asm volatile("cp.async.commit_group;")
#define CP_WAIT(n)  asm volatile("cp.async.wait_group %0;" :: "n"(n))

#define LDSM4(r, a)                                                              \
    asm volatile("ldmatrix.sync.aligned.m8n8.x4.shared.b16 {%0,%1,%2,%3}, [%4];" \
                 : "=r"((r)[0]), "=r"((r)[1]), "=r"((r)[2]), "=r"((r)[3])        \
                 : "r"(a))

__device__ __forceinline__ void mma_acc(float* d, const uint32_t* a, uint32_t b0, uint32_t b1) {
    asm("mma.sync.aligned.m16n8k16.row.col.f32.f16.f16.f32 "
        "{%0,%1,%2,%3},{%4,%5,%6,%7},{%8,%9},{%0,%1,%2,%3};"
        : "+f"(d[0]), "+f"(d[1]), "+f"(d[2]), "+f"(d[3])
        : "r"(a[0]), "r"(a[1]), "r"(a[2]), "r"(a[3]), "r"(b0), "r"(b1));
}

// octet table: for i=0..31, jb=i,i+8,.. (<32): entry = i<<8 | jb. 80 entries.
// counts per i: 4 (i<8), 3 (8..15), 2 (16..23), 1 (24..31)
// closed-form entry for octet index o:
__device__ __forceinline__ uint32_t oct_entry(int o) {
    int i, r;
    if (o < 32)      { i = o >> 2;           r = o & 3; }
    else if (o < 56) { i = 8 + (o - 32) / 3; r = (o - 32) % 3; }
    else if (o < 72) { i = 16 + ((o - 56) >> 1); r = (o - 56) & 1; }
    else             { i = 24 + (o - 72);    r = 0; }
    return ((uint32_t)i << 8) | (uint32_t)(i + 8 * r);
}
__device__ __forceinline__ void build_oct(uint32_t* oct) {
    for (int o = 0; o < NOCT; o++) oct[o] = oct_entry(o);
}

// ---------------- SMEM layout (main kernel) ----------------
#define ROWB    256
#define BUF_SZ  (128 * ROWB)                  // 32768 per stage buffer
#define OFF_PS  (NBUF * BUF_SZ)               // 98304 : float pS[128][41] zero-padded
#define OFF_CS  (OFF_PS + 128 * PSTR * 4)     // float cS[128][9]
#define OFF_TAB (OFF_CS + 128 * 9 * 4)        // u32 oct[80]
#define SMEM_TOTAL (OFF_TAB + NOCT * 4)       // 124224 bytes

// =====================================================================
// Prep: coalesced symmetric fold, MLP-optimized. block = (l, chunk c).
// 256 threads: h = tid>>7 selects kk-half, n = tid&127 the W column.
// =====================================================================
__global__ void __launch_bounds__(256) fipp_prep_kernel(const float* __restrict__ W)
{
    __shared__ float sbuf[32][129];
    const int tid = threadIdx.x;
    const int n = tid & 127, h = tid >> 7;

    const int l = blockIdx.x / KCHL, c = blockIdx.x % KCHL;
    const float* Wl = W + (size_t)l * 1024 * 128 + n;

    // each thread: 16 kk's, fully unrolled for max loads-in-flight
    #pragma unroll
    for (int kq = 0; kq < 16; kq++) {
        const int kk = h * 16 + kq;
        const int kg = 32 * c + kk;
        const uint32_t e = oct_entry(kg >> 3);
        const int i = e >> 8, j = (int)(e & 255) + (kg & 7);
        float v = 0.0f;
        if (j < 32) {
            v = Wl[(size_t)(i * 32 + j) * 128];
            if (i != j) v += Wl[(size_t)(j * 32 + i) * 128];
        }
        sbuf[kk][n] = 64.0f * v;
    }
    __syncthreads();

    // write image: thread (h, n) emits 8 u32 (two uint4), contiguous per n
    uint32_t* oh = g_Wt + (size_t)blockIdx.x * 2048 + n * 16 + h * 8;
    #pragma unroll
    for (int v4 = 0; v4 < 2; v4++) {
        uint32_t r[4];
        #pragma unroll
        for (int d = 0; d < 4; d++) {
            const int q = h * 8 + v4 * 4 + d;
            r[d] = pack_f16x2(sbuf[2 * q][n], sbuf[2 * q + 1][n]);
        }
        *(uint4*)(oh + v4 * 4) = make_uint4(r[0], r[1], r[2], r[3]);
    }
}

// =====================================================================
// Main: fp16 HMMA GEMM over octet-aligned symmetric pair axis.
// CTA: M=128, N=128, K = 8 l x 640 (40 stages of 128 cols).
// 8 warps, warp tile M=32 x N=64. A + B fragment groups double-buffered.
// =====================================================================
__global__ void __launch_bounds__(256, 1)
fipp_mma_kernel(const float* __restrict__ ctrl, const float* __restrict__ pert)
{
    extern __shared__ char smem[];
    float*    pS  = (float*)(smem + OFF_PS);   // [128][41] zero-padded
    float*    cS  = (float*)(smem + OFF_CS);   // [128][9]
    uint32_t* tab = (uint32_t*)(smem + OFF_TAB);
    const uint32_t sb = s2u(smem);
    const int tid = threadIdx.x, wid = tid >> 5, lane = tid & 31;
    const int wm = wid & 3, wn = wid >> 2;   // 4 M-bands x 2 N-bands (32x64)
    const int g = lane >> 2, t = lane & 3;
    const int bm0 = blockIdx.x * 128, l_base = blockIdx.y * LPER;

    // stage loader: 4 chunk images (32KB) -> [n=128][k=128] tile, swizzled
    auto issueW = [&](int st, int buf) {
        const int l = st / 5, c0 = (st % 5) * 4;
        const uint32_t* gh = g_Wt + (size_t)((l_base + l) * KCHL + c0) * 2048;
        const uint32_t bbase = sb + (uint32_t)buf * BUF_SZ;
        #pragma unroll
        for (int q = 0; q < 8; q++) {
            const int e = q * 256 + tid;        // 0..2047 16B units
            const int c = e >> 9, gi = e & 511;
            const int n = gi >> 2, w4 = gi & 3;
            const int u = ((4 * c + w4) ^ (n & 7));
            cp16(bbase + (uint32_t)(n * ROWB + (u << 4)), gh + 4 * e);
        }
        CP_COMMIT();
    };

    issueW(0, 0);

    // one-time fills: pS (zero-padded), cS, octet table
    for (int e = tid; e < 128 * PSTR; e += 256) {
        const int r = e / PSTR, j = e % PSTR;
        pS[e] = (j < 32) ? pert[(size_t)(bm0 + r) * PP + j] : 0.0f;
    }
    for (int e = tid; e < 128 * 8; e += 256) {
        const int r = e >> 3, q = e & 7;
        cS[r * 9 + q] = ctrl[(size_t)(bm0 + r) * LL + l_base + q];
    }
    if (tid < NOCT) tab[tid] = oct_entry(tid);

    issueW(1, 1);
    __syncthreads();   // pS/cS/tab ready

    int rows[4];
    #pragma unroll
    for (int rr = 0; rr < 4; rr++) rows[rr] = wm * 32 + rr * 8 + g;

    float acc[2][8][4];
    #pragma unroll
    for (int m = 0; m < 2; m++)
        #pragma unroll
        for (int nt = 0; nt < 8; nt++)
            #pragma unroll
            for (int k = 0; k < 4; k++) acc[m][nt][k] = 0.f;

    float clv[4];

    // ldmatrix addressing
    const int nlocal = ((lane >> 4) << 3) | (lane & 7);
    const int hk = (lane >> 3) & 1;
    const int sx = lane & 7;
    const uint32_t rba = (uint32_t)((wn * 64 + nlocal) * ROWB);

    for (int st = 0; st < NSTAGE; st++) {
        const int buf = st % NBUF;
        if (st + 2 < NSTAGE) { CP_WAIT(1); } else { CP_WAIT(0); }
        __syncthreads();
        if (st + 2 < NSTAGE) issueW(st + 2, (st + 2) % NBUF);

        const int l = st / 5, stq = st % 5;
        const int obase = stq * 16;
        if (stq == 0) {
            #pragma unroll
            for (int rr = 0; rr < 4; rr++) clv[rr] = cS[rows[rr] * 9 + l];
        }
        const uint32_t Bt = sb + (uint32_t)buf * BUF_SZ + rba;

        auto ld_group = [&](int gidx, uint32_t* bh) {
            const uint32_t uu = (uint32_t)(((gidx << 1) + hk) ^ sx) << 4;
            #pragma unroll
            for (int ntp = 0; ntp < 4; ntp++)
                LDSM4(bh + 4 * ntp, Bt + (uint32_t)(ntp * 16 * ROWB) + uu);
        };
        // A build: octet pair (o0 = low 8 k's, o1 = high 8 k's) of group gidx
        auto a_build = [&](int gidx, uint32_t* av) {  // av[8] = a[m][r4]
            const uint32_t e0 = tab[obase + 2 * gidx];
            const uint32_t e1 = tab[obase + 2 * gidx + 1];
            const int i0 = e0 >> 8, j0 = (int)(e0 & 255) + 2 * t;
            const int i1 = e1 >> 8, j1 = (int)(e1 & 255) + 2 * t;
            #pragma unroll
            for (int rr = 0; rr < 4; rr++) {
                const float* pr = pS + rows[rr] * PSTR;
                const float s0 = clv[rr] * pr[i0];
                const float s1 = clv[rr] * pr[i1];
                av[(rr >> 1) * 4 + (rr & 1)]     = pack_f16x2(s0 * pr[j0], s0 * pr[j0 + 1]);
                av[(rr >> 1) * 4 + 2 + (rr & 1)] = pack_f16x2(s1 * pr[j1], s1 * pr[j1 + 1]);
            }
        };

        uint32_t bA[16], bB[16], aA[8], aB[8];
        ld_group(0, bA);
        a_build(0, aA);

        #pragma unroll
        for (int gidx = 0; gidx < 8; gidx++) {
            uint32_t* curB = (gidx & 1) ? bB : bA;
            uint32_t* nxtB = (gidx & 1) ? bA : bB;
            uint32_t* curA = (gidx & 1) ? aB : aA;
            uint32_t* nxtA = (gidx & 1) ? aA : aB;
            if (gidx + 1 < 8) { ld_group(gidx + 1, nxtB); a_build(gidx + 1, nxtA); }

            #pragma unroll
            for (int m = 0; m < 2; m++)
                #pragma unroll
                for (int nt = 0; nt < 8; nt++)
                    mma_acc(acc[m][nt], curA + 4 * m, curB[2 * nt], curB[2 * nt + 1]);
        }
    }

    // epilogue -> split-K partials (undo the *64 on W)
    #pragma unroll
    for (int m = 0; m < 2; m++)
        #pragma unroll
        for (int rh = 0; rh < 2; rh++) {
            const int rowloc = wm * 32 + m * 16 + rh * 8 + g;
            float* dst = g_partial + ((size_t)blockIdx.y * BB + bm0 + rowloc) * LL;
            #pragma unroll
            for (int nt = 0; nt < 8; nt++) {
                const int col = wn * 64 + nt * 8 + 2 * t;
                float2 v;
                v.x = acc[m][nt][rh ? 2 : 0] * 0.015625f;
                v.y = acc[m][nt][rh ? 3 : 1] * 0.015625f;
                *(float2*)(dst + col) = v;
            }
        }
}

// =====================================================================
// Reduce: sum 16 split-K partials + bias
// =====================================================================
__global__ void __launch_bounds__(256)
fipp_reduce_kernel(const float* __restrict__ bias, float* __restrict__ out)
{
    const int i4 = blockIdx.x * blockDim.x + threadIdx.x;
    float4 acc = *(const float4*)(bias + ((i4 * 4) & (LL - 1)));
    #pragma unroll
    for (int s = 0; s < SPLITS; s++) {
        const float4 v = *(const float4*)(g_partial + (size_t)s * (BB * LL) + (size_t)i4 * 4);
        acc.x += v.x; acc.y += v.y; acc.z += v.z; acc.w += v.w;
    }
    *(float4*)(out + (size_t)i4 * 4) = acc;
}

extern "C" void kernel_launch(void* const* d_in, const int* in_sizes, int n_in,
                              void* d_out, int out_size)
{
    const float* ctrl = (const float*)d_in[0];   // (1024,128)
    const float* pert = (const float*)d_in[1];   // (1024,32)
    const float* W    = (const float*)d_in[2];   // (131072,128)
    const float* bias = (const float*)d_in[3];   // (128,)
    float* out = (float*)d_out;                  // (1024,128)

    cudaFuncSetAttribute(fipp_mma_kernel,
                         cudaFuncAttributeMaxDynamicSharedMemorySize, SMEM_TOTAL);

    fipp_prep_kernel<<<128 * KCHL, 256>>>(W);
    fipp_mma_kernel<<<dim3(MTILES, SPLITS), 256, SMEM_TOTAL>>>(ctrl, pert);
    fipp_reduce_kernel<<<(BB * LL) / 4 / 256, 256>>>(bias, out);
}